// round 7
// baseline (speedup 1.0000x reference)
#include <cuda_runtime.h>
#include <cfloat>

// Problem geometry (fixed by the reference): planes of 128x128, B*C planes.
constexpr int W_DIM   = 128;
constexpr int HW      = 128 * 128;   // 16384 elements per (b,c) plane
constexpr int V4      = HW / 4;      // 4096 float4 per plane
constexpr int LPER    = V4 / 32;     // 16 float4 per lane (one warp per plane)
constexpr int WPC     = 4;           // warps per CTA
constexpr int THREADS = WPC * 32;    // 128

// Butterfly reductions: ALL lanes end with the result (no broadcast needed).
__device__ __forceinline__ float bfly_sum(float v) {
    #pragma unroll
    for (int o = 16; o > 0; o >>= 1) v += __shfl_xor_sync(0xffffffffu, v, o);
    return v;
}
__device__ __forceinline__ float bfly_min(float v) {
    #pragma unroll
    for (int o = 16; o > 0; o >>= 1) v = fminf(v, __shfl_xor_sync(0xffffffffu, v, o));
    return v;
}
__device__ __forceinline__ float bfly_max(float v) {
    #pragma unroll
    for (int o = 16; o > 0; o >>= 1) v = fmaxf(v, __shfl_xor_sync(0xffffffffu, v, o));
    return v;
}

__global__ __launch_bounds__(THREADS)
void hm2kp_kernel(const float* __restrict__ in,
                  float* __restrict__ map_out,
                  float* __restrict__ kp_out,
                  float* __restrict__ zeta_out)
{
    const int lane  = threadIdx.x & 31;
    const int plane = blockIdx.x * WPC + (threadIdx.x >> 5);  // one warp per plane

    const float4* __restrict__ inp  = reinterpret_cast<const float4*>(in) + (size_t)plane * V4;
    float4* __restrict__       outp = reinterpret_cast<float4*>(map_out) + (size_t)plane * V4;

    // ---- Phase 1: stage plane into registers; local min/max.
    //      No block barrier anywhere: this warp's stream is independent of
    //      all others, so per-warp reduce stalls are covered by neighbors. ----
    float4 v[LPER];
    float lmin = FLT_MAX, lmax = -FLT_MAX;
    #pragma unroll
    for (int j = 0; j < LPER; ++j) {
        v[j] = __ldcs(&inp[lane + 32 * j]);
        lmin = fminf(lmin, fminf(fminf(v[j].x, v[j].y), fminf(v[j].z, v[j].w)));
        lmax = fmaxf(lmax, fmaxf(fmaxf(v[j].x, v[j].y), fmaxf(v[j].z, v[j].w)));
    }

    // ---- Warp-only min/max reduce (butterfly: every lane has the result) ----
    const float bmin = bfly_min(lmin);
    const float rcp  = 1.0f / bfly_max(lmax);   // reference divides by max (not max-min)

    // ---- Phase 2: normalize, store, accumulate sums on NORMALIZED values ----
    float sum = 0.f, sx = 0.f, sy = 0.f;
    #pragma unroll
    for (int j = 0; j < LPER; ++j) {
        const int i4 = lane + 32 * j;
        const float m0 = (v[j].x - bmin) * rcp;
        const float m1 = (v[j].y - bmin) * rcp;
        const float m2 = (v[j].z - bmin) * rcp;
        const float m3 = (v[j].w - bmin) * rcp;

        const int base = i4 << 2;                     // element index in plane
        const float x0 = (float)(base & (W_DIM - 1));
        const float yy = (float)(base >> 7);          // row (constant per float4)

        const float s4 = (m0 + m1) + (m2 + m3);
        sum += s4;
        sx  += m0 * x0 + m1 * (x0 + 1.f) + m2 * (x0 + 2.f) + m3 * (x0 + 3.f);
        sy  += s4 * yy;

        __stcs(&outp[i4], make_float4(m0, m1, m2, m3));
    }

    // ---- Warp-only sum reduce; lane 0 writes the tiny outputs ----
    sum = bfly_sum(sum);
    sx  = bfly_sum(sx);
    sy  = bfly_sum(sy);
    if (lane == 0) {
        kp_out[(size_t)plane * 2 + 0] = rintf(sx / sum);  // round(get_kp_x / zeta)
        kp_out[(size_t)plane * 2 + 1] = rintf(sy / sum);  // round(get_kp_y / zeta)
        zeta_out[plane] = sum;
    }
}

extern "C" void kernel_launch(void* const* d_in, const int* in_sizes, int n_in,
                              void* d_out, int out_size)
{
    const float* in = (const float*)d_in[0];
    const int total  = in_sizes[0];        // B*C*H*W
    const int planes = total / HW;         // B*C = 6400

    float* map  = (float*)d_out;                       // [B,C,H,W]
    float* kp   = map + (size_t)total;                 // [B,C,2]
    float* zeta = kp + (size_t)planes * 2;             // [B,C]

    hm2kp_kernel<<<planes / WPC, THREADS>>>(in, map, kp, zeta);
}

// round 8
// speedup vs baseline: 5.7368x; 5.7368x over previous
#include <cuda_runtime.h>
#include <cfloat>

// Problem geometry (fixed by the reference): planes of 128x128, B*C planes.
constexpr int W_DIM   = 128;
constexpr int HW      = 128 * 128;     // 16384 elements per (b,c) plane
constexpr int THREADS = 1024;
constexpr int V4      = HW / 4;        // 4096 float4 per plane
constexpr int PER     = V4 / THREADS;  // 4 float4 per thread

__device__ __forceinline__ float warp_sum(float v) {
    #pragma unroll
    for (int o = 16; o > 0; o >>= 1) v += __shfl_down_sync(0xffffffffu, v, o);
    return v;
}
__device__ __forceinline__ float warp_min(float v) {
    #pragma unroll
    for (int o = 16; o > 0; o >>= 1) v = fminf(v, __shfl_down_sync(0xffffffffu, v, o));
    return v;
}
__device__ __forceinline__ float warp_max(float v) {
    #pragma unroll
    for (int o = 16; o > 0; o >>= 1) v = fmaxf(v, __shfl_down_sync(0xffffffffu, v, o));
    return v;
}

__global__ __launch_bounds__(THREADS, 2)
void hm2kp_kernel(const float* __restrict__ in,
                  float* __restrict__ map_out,
                  float* __restrict__ kp_out,
                  float* __restrict__ zeta_out)
{
    __shared__ float s_r0[32], s_r1[32], s_r2[32];
    __shared__ float s_bmin, s_rcp;

    const int bc   = blockIdx.x;
    const int tid  = threadIdx.x;
    const int lane = tid & 31;
    const int wid  = tid >> 5;

    const float4* __restrict__ inp  = reinterpret_cast<const float4*>(in) + (size_t)bc * V4;
    float4* __restrict__       outp = reinterpret_cast<float4*>(map_out) + (size_t)bc * V4;

    // ---- Phase 1: load whole plane into registers (16 regs/thread), min/max ----
    float4 v[PER];
    float lmin = FLT_MAX, lmax = -FLT_MAX;
    #pragma unroll
    for (int i = 0; i < PER; ++i) {
        v[i] = __ldcs(&inp[tid + i * THREADS]);
        lmin = fminf(lmin, fminf(fminf(v[i].x, v[i].y), fminf(v[i].z, v[i].w)));
        lmax = fmaxf(lmax, fmaxf(fmaxf(v[i].x, v[i].y), fmaxf(v[i].z, v[i].w)));
    }

    // ---- Block reduce min/max (32 warps) ----
    lmin = warp_min(lmin);
    lmax = warp_max(lmax);
    if (lane == 0) { s_r0[wid] = lmin; s_r1[wid] = lmax; }
    __syncthreads();
    if (wid == 0) {
        float m0 = warp_min(s_r0[lane]);
        float m1 = warp_max(s_r1[lane]);
        if (lane == 0) { s_bmin = m0; s_rcp = 1.0f / m1; }  // ref divides by max (not max-min)
    }
    __syncthreads();

    const float bmin = s_bmin;
    const float rcp  = s_rcp;

    // ---- Phase 2: normalize, stream out, accumulate the three reductions
    //      on NORMALIZED values (matches reference numerics, rel_err ~6e-8). ----
    float sum = 0.f, sx = 0.f, sy = 0.f;
    #pragma unroll
    for (int i = 0; i < PER; ++i) {
        const int i4 = tid + i * THREADS;

        const float m0 = (v[i].x - bmin) * rcp;
        const float m1 = (v[i].y - bmin) * rcp;
        const float m2 = (v[i].z - bmin) * rcp;
        const float m3 = (v[i].w - bmin) * rcp;

        const int base = i4 << 2;                     // element index in plane
        const float x0 = (float)(base & (W_DIM - 1));
        const float yy = (float)(base >> 7);          // row (constant per float4)

        const float s4 = (m0 + m1) + (m2 + m3);
        sum += s4;
        sx  += m0 * x0 + m1 * (x0 + 1.f) + m2 * (x0 + 2.f) + m3 * (x0 + 3.f);
        sy  += s4 * yy;

        __stcs(&outp[i4], make_float4(m0, m1, m2, m3));
    }

    // ---- Block reduce the three sums ----
    sum = warp_sum(sum);
    sx  = warp_sum(sx);
    sy  = warp_sum(sy);
    if (lane == 0) { s_r0[wid] = sum; s_r1[wid] = sx; s_r2[wid] = sy; }
    __syncthreads();
    if (wid == 0) {
        float a = warp_sum(s_r0[lane]);
        float b = warp_sum(s_r1[lane]);
        float c = warp_sum(s_r2[lane]);
        if (lane == 0) {
            kp_out[(size_t)bc * 2 + 0] = rintf(b / a);  // round(get_kp_x / zeta)
            kp_out[(size_t)bc * 2 + 1] = rintf(c / a);  // round(get_kp_y / zeta)
            zeta_out[bc] = a;
        }
    }
}

extern "C" void kernel_launch(void* const* d_in, const int* in_sizes, int n_in,
                              void* d_out, int out_size)
{
    const float* in = (const float*)d_in[0];
    const int total  = in_sizes[0];        // B*C*H*W
    const int planes = total / HW;         // B*C = 6400

    float* map  = (float*)d_out;                       // [B,C,H,W]
    float* kp   = map + (size_t)total;                 // [B,C,2]
    float* zeta = kp + (size_t)planes * 2;             // [B,C]

    hm2kp_kernel<<<planes, THREADS>>>(in, map, kp, zeta);
}

// round 9
// speedup vs baseline: 5.9142x; 1.0309x over previous
#include <cuda_runtime.h>
#include <cfloat>

// Problem geometry (fixed by the reference): planes of 128x128, B*C planes.
constexpr int W_DIM   = 128;
constexpr int HW      = 128 * 128;     // 16384 elements per (b,c) plane
constexpr int THREADS = 512;           // 16 warps: this reduction ordering
                                       // reproduces the reference keypoints
                                       // exactly (rel_err ~6e-8 measured)
constexpr int V4      = HW / 4;        // 4096 float4 per plane
constexpr int PER     = V4 / THREADS;  // 8 float4 per thread

__device__ __forceinline__ float warp_sum(float v) {
    #pragma unroll
    for (int o = 16; o > 0; o >>= 1) v += __shfl_down_sync(0xffffffffu, v, o);
    return v;
}
__device__ __forceinline__ float warp_min(float v) {
    #pragma unroll
    for (int o = 16; o > 0; o >>= 1) v = fminf(v, __shfl_down_sync(0xffffffffu, v, o));
    return v;
}
__device__ __forceinline__ float warp_max(float v) {
    #pragma unroll
    for (int o = 16; o > 0; o >>= 1) v = fmaxf(v, __shfl_down_sync(0xffffffffu, v, o));
    return v;
}

__global__ __launch_bounds__(THREADS)
void hm2kp_kernel(const float* __restrict__ in,
                  float* __restrict__ map_out,
                  float* __restrict__ kp_out,
                  float* __restrict__ zeta_out)
{
    __shared__ float s_r0[16], s_r1[16], s_r2[16];
    __shared__ float s_bmin, s_rcp;

    const int bc   = blockIdx.x;
    const int tid  = threadIdx.x;
    const int lane = tid & 31;
    const int wid  = tid >> 5;

    const float4* __restrict__ inp  = reinterpret_cast<const float4*>(in) + (size_t)bc * V4;
    float4* __restrict__       outp = reinterpret_cast<float4*>(map_out) + (size_t)bc * V4;

    // ---- Phase 1: stage whole plane in registers (32 regs/thread), min/max.
    //      __ldcs: no reuse, keep the stream out of L2's way. ----
    float4 v[PER];
    float lmin = FLT_MAX, lmax = -FLT_MAX;
    #pragma unroll
    for (int i = 0; i < PER; ++i) {
        v[i] = __ldcs(&inp[tid + i * THREADS]);
        lmin = fminf(lmin, fminf(fminf(v[i].x, v[i].y), fminf(v[i].z, v[i].w)));
        lmax = fmaxf(lmax, fmaxf(fmaxf(v[i].x, v[i].y), fmaxf(v[i].z, v[i].w)));
    }

    // ---- Block reduce min/max (16 warps) ----
    lmin = warp_min(lmin);
    lmax = warp_max(lmax);
    if (lane == 0) { s_r0[wid] = lmin; s_r1[wid] = lmax; }
    __syncthreads();
    if (wid == 0) {
        float m0 = (lane < 16) ? s_r0[lane] :  FLT_MAX;
        float m1 = (lane < 16) ? s_r1[lane] : -FLT_MAX;
        m0 = warp_min(m0);
        m1 = warp_max(m1);
        if (lane == 0) { s_bmin = m0; s_rcp = 1.0f / m1; }  // ref divides by max (not max-min)
    }
    __syncthreads();

    const float bmin = s_bmin;
    const float rcp  = s_rcp;

    // ---- Phase 2: normalize, stream out, accumulate the three reductions
    //      on NORMALIZED values in the exact ordering that reproduces the
    //      reference keypoints (512 thr, PER=8, tid-strided). ----
    float sum = 0.f, sx = 0.f, sy = 0.f;
    #pragma unroll
    for (int i = 0; i < PER; ++i) {
        const int i4 = tid + i * THREADS;

        const float m0 = (v[i].x - bmin) * rcp;
        const float m1 = (v[i].y - bmin) * rcp;
        const float m2 = (v[i].z - bmin) * rcp;
        const float m3 = (v[i].w - bmin) * rcp;

        const int base = i4 << 2;                     // element index in plane
        const float x0 = (float)(base & (W_DIM - 1));
        const float yy = (float)(base >> 7);          // row (constant per float4)

        const float s4 = (m0 + m1) + (m2 + m3);
        sum += s4;
        sx  += m0 * x0 + m1 * (x0 + 1.f) + m2 * (x0 + 2.f) + m3 * (x0 + 3.f);
        sy  += s4 * yy;

        __stcs(&outp[i4], make_float4(m0, m1, m2, m3));
    }

    // ---- Block reduce the three sums (16 warps) ----
    sum = warp_sum(sum);
    sx  = warp_sum(sx);
    sy  = warp_sum(sy);
    if (lane == 0) { s_r0[wid] = sum; s_r1[wid] = sx; s_r2[wid] = sy; }
    __syncthreads();
    if (wid == 0) {
        float a = (lane < 16) ? s_r0[lane] : 0.f;
        float b = (lane < 16) ? s_r1[lane] : 0.f;
        float c = (lane < 16) ? s_r2[lane] : 0.f;
        a = warp_sum(a);
        b = warp_sum(b);
        c = warp_sum(c);
        if (lane == 0) {
            kp_out[(size_t)bc * 2 + 0] = rintf(b / a);  // round(get_kp_x / zeta)
            kp_out[(size_t)bc * 2 + 1] = rintf(c / a);  // round(get_kp_y / zeta)
            zeta_out[bc] = a;
        }
    }
}

extern "C" void kernel_launch(void* const* d_in, const int* in_sizes, int n_in,
                              void* d_out, int out_size)
{
    const float* in = (const float*)d_in[0];
    const int total  = in_sizes[0];        // B*C*H*W
    const int planes = total / HW;         // B*C = 6400

    float* map  = (float*)d_out;                       // [B,C,H,W]
    float* kp   = map + (size_t)total;                 // [B,C,2]
    float* zeta = kp + (size_t)planes * 2;             // [B,C]

    hm2kp_kernel<<<planes, THREADS>>>(in, map, kp, zeta);
}